// round 11
// baseline (speedup 1.0000x reference)
#include <cuda_runtime.h>

#define HW 50176
#define W_ 224
#define H_ 224
#define SEGS 8
#define SEG_ROWS 28          // 224 / 8
#define QPR 56               // quads per row (224/4)
#define RG  56               // 4-row groups per plane (224/4)
#define RBLK 1184            // persistent reduce blocks = 148 SMs * 8 CTAs

__device__ float g_part[1024 * SEGS];   // per-(image,segment) partial sums
__device__ float g_gm[1024];            // per-image gray mean
__device__ int   g_cnt[1024];           // arrival tickets (zero-init, self-resetting)

// ---------------------------------------------------------------------------
// Kernel 1: persistent single-wave reduction + fused gm finalize.
// Per-work-item body is FROZEN (identical 256-thread loop and accumulation
// order as R10 => g_gm bitwise identical). Only the block->work mapping
// changed: grid-stride over (b,s) so the whole kernel is exactly one wave.
// ---------------------------------------------------------------------------
__global__ void __launch_bounds__(256)
reduce_kernel(const float* __restrict__ x,
              const float* __restrict__ mean,
              const float* __restrict__ stdv,
              int nwork) {
    __shared__ float red[8];
    __shared__ bool amLast;

    const float gw0 = 0.299f * stdv[0];
    const float gw1 = 0.587f * stdv[1];
    const float gw2 = 0.114f * stdv[2];
    const int npix = SEG_ROWS * W_ / 4;   // 1568 quads

    for (int w = blockIdx.x; w < nwork; w += gridDim.x) {
        const int b = w >> 3;
        const int s = w & 7;
        const float* p = x + (size_t)b * 3 * HW + s * SEG_ROWS * W_;

        float acc = 0.f;
        int i = threadIdx.x;
        // stage-0 / stage-1 prologue (tid+256 < 1568 always)
        float4 a0 = *(const float4*)(p + i * 4);
        float4 a1 = *(const float4*)(p + HW + i * 4);
        float4 a2 = *(const float4*)(p + 2 * HW + i * 4);
        float4 b0 = *(const float4*)(p + (i + 256) * 4);
        float4 b1 = *(const float4*)(p + HW + (i + 256) * 4);
        float4 b2 = *(const float4*)(p + 2 * HW + (i + 256) * 4);

        while (i < npix) {
            const int pf = i + 512;        // distance-2 prefetch
            float4 c0, c1, c2;
            if (pf < npix) {
                c0 = *(const float4*)(p + pf * 4);
                c1 = *(const float4*)(p + HW + pf * 4);
                c2 = *(const float4*)(p + 2 * HW + pf * 4);
            }

            const int pix = i * 4;
            const int lr = pix / W_;
            const int cc0 = pix - lr * W_;
            const int gr = s * SEG_ROWS + lr;
            const float ny = (gr == 0 || gr == H_ - 1) ? 2.f : 3.f;

            float e0[4] = {a0.x, a0.y, a0.z, a0.w};
            float e1[4] = {a1.x, a1.y, a1.z, a1.w};
            float e2[4] = {a2.x, a2.y, a2.z, a2.w};

            if (cc0 != 0 && cc0 != W_ - 4) {
                const float coef = 0.64f + 0.36f * (ny * 3.f + 4.f) * (1.f / 13.f);
#pragma unroll
                for (int j = 0; j < 4; j++) {
                    const float gx = gw0 * e0[j] + gw1 * e1[j] + gw2 * e2[j];
                    acc += coef * gx;
                }
            } else {
#pragma unroll
                for (int j = 0; j < 4; j++) {
                    const int c = cc0 + j;
                    const float nxw = (c == 0 || c == W_ - 1) ? 2.f : 3.f;
                    const float coef = 0.64f + 0.36f * (ny * nxw + 4.f) * (1.f / 13.f);
                    const float gx = gw0 * e0[j] + gw1 * e1[j] + gw2 * e2[j];
                    acc += coef * gx;
                }
            }

            a0 = b0; a1 = b1; a2 = b2;
            b0 = c0; b1 = c1; b2 = c2;
            i += 256;
        }

#pragma unroll
        for (int off = 16; off > 0; off >>= 1)
            acc += __shfl_down_sync(0xffffffffu, acc, off);
        const int lane = threadIdx.x & 31;
        const int warp = threadIdx.x >> 5;
        if (lane == 0) red[warp] = acc;
        __syncthreads();
        if (threadIdx.x == 0) {
            float t = 0.f;
#pragma unroll
            for (int k = 0; k < 8; k++) t += red[k];
            g_part[w] = t;
            __threadfence();
            const int old = atomicAdd(&g_cnt[b], 1);
            amLast = (old == SEGS - 1);
        }
        __syncthreads();
        if (amLast && threadIdx.x == 0) {
            __threadfence();
            float ps = 0.f;
#pragma unroll
            for (int k = 0; k < SEGS; k++) ps += g_part[b * SEGS + k];
            const double SC = 0.64 * (double)HW + 0.36 * (448900.0 + 4.0 * HW) / 13.0;
            const float cm = 0.299f * mean[0] + 0.587f * mean[1] + 0.114f * mean[2];
            g_gm[b] = (ps + cm * (float)SC) * (1.0f / (float)HW);
            g_cnt[b] = 0;                  // reset for next graph replay
        }
        __syncthreads();                   // protect red[]/amLast across items
    }
}

// ---------------------------------------------------------------------------
// Kernel 2: R6 main with __launch_bounds__(256,5) -> <=51 regs, 5 CTAs/SM.
// Everything else byte-for-byte identical.
// ---------------------------------------------------------------------------
__global__ void __launch_bounds__(256, 5)
main_kernel(const float* __restrict__ x,
            const float* __restrict__ mean,
            const float* __restrict__ stdv,
            float* __restrict__ out,
            int nplanes) {
    const int idx = blockIdx.x * 256 + threadIdx.x;
    const int q = idx % QPR;                  // column quad 0..55
    const int t2 = idx / QPR;
    const int rg = t2 % RG;                   // row group 0..55
    int plane = t2 / RG;
    if (plane >= nplanes) return;
    plane = nplanes - 1 - plane;              // reverse traversal for L2 reuse

    const int b = plane / 3;
    const int ch = plane - b * 3;
    const float m = mean[ch];
    const float sd = stdv[ch];
    const float inv_sd = 1.0f / sd;
    const float nmo = -m * inv_sd;
    const float gm = g_gm[b];

    const float C1 = (float)(0.4096 * (0.64 + 1.44 / 13.0));
    const float C2 = (float)(0.4096 * 0.36 / 13.0);
    const float G  = (float)(0.64 * 0.36) * gm;

    const float* p = x + (size_t)plane * HW;
    const int c4 = q * 4;
    const int r0 = rg * 4;

    // ---- 6 source rows (r0-1 .. r0+4), front-batched loads, affine ----
    float4 v[6];
#pragma unroll
    for (int k = 0; k < 6; k++) {
        const int row = r0 - 1 + k;
        if (row >= 0 && row < H_) {
            float4 u = *(const float4*)(p + row * W_ + c4);
            v[k].x = fmaf(u.x, sd, m);
            v[k].y = fmaf(u.y, sd, m);
            v[k].z = fmaf(u.z, sd, m);
            v[k].w = fmaf(u.w, sd, m);
        } else {
            v[k] = make_float4(0.f, 0.f, 0.f, 0.f);
        }
    }

    // ---- horizontal halos: shuffle interior, scalar LDG only at edges ----
    const unsigned lane = threadIdx.x & 31;
    float L[6], R[6];
#pragma unroll
    for (int k = 0; k < 6; k++) {
        L[k] = __shfl_up_sync(0xffffffffu, v[k].w, 1);
        R[k] = __shfl_down_sync(0xffffffffu, v[k].x, 1);
    }
    if (q == 0) {
#pragma unroll
        for (int k = 0; k < 6; k++) L[k] = 0.f;
    } else if (lane == 0) {
#pragma unroll
        for (int k = 0; k < 6; k++) {
            const int row = r0 - 1 + k;
            L[k] = (row >= 0 && row < H_) ? fmaf(p[row * W_ + c4 - 1], sd, m) : 0.f;
        }
    }
    if (q == QPR - 1) {
#pragma unroll
        for (int k = 0; k < 6; k++) R[k] = 0.f;
    } else if (lane == 31) {
#pragma unroll
        for (int k = 0; k < 6; k++) {
            const int row = r0 - 1 + k;
            R[k] = (row >= 0 && row < H_) ? fmaf(p[row * W_ + c4 + 4], sd, m) : 0.f;
        }
    }

    // ---- 4 output rows ----
    float* ob = out + (size_t)plane * HW + r0 * W_ + c4;

#pragma unroll
    for (int o = 0; o < 4; o++) {
        const float cs0 = L[o]   + L[o + 1]   + L[o + 2];
        const float cs1 = v[o].x + v[o + 1].x + v[o + 2].x;
        const float cs2 = v[o].y + v[o + 1].y + v[o + 2].y;
        const float cs3 = v[o].z + v[o + 1].z + v[o + 2].z;
        const float cs4 = v[o].w + v[o + 1].w + v[o + 2].w;
        const float cs5 = R[o]   + R[o + 1]   + R[o + 2];

        const float cen[4] = {v[o + 1].x, v[o + 1].y, v[o + 1].z, v[o + 1].w};
        const float tot[4] = {cs0 + cs1 + cs2, cs1 + cs2 + cs3,
                              cs2 + cs3 + cs4, cs3 + cs4 + cs5};

        float4 ov;
        float* op = (float*)&ov;
#pragma unroll
        for (int j = 0; j < 4; j++) {
            const float y2 = fmaf(cen[j], C1, fmaf(tot[j], C2, G));
            const float z = (y2 < 0.3f) ? y2 : 1.0f - y2;
            op[j] = fmaf(z, inv_sd, nmo);
        }
        __stwt((float4*)(ob + o * W_), ov);    // write-through, no L2 allocate
    }
}

extern "C" void kernel_launch(void* const* d_in, const int* in_sizes, int n_in,
                              void* d_out, int out_size) {
    const float* x    = (const float*)d_in[0];
    const float* mean = (const float*)d_in[1];
    const float* stdv = (const float*)d_in[2];
    float* out = (float*)d_out;

    const int B = in_sizes[0] / (3 * HW);
    const int nplanes = B * 3;
    const int nwork = B * SEGS;

    const int rblocks = nwork < RBLK ? nwork : RBLK;
    reduce_kernel<<<rblocks, 256>>>(x, mean, stdv, nwork);

    const int total = nplanes * RG * QPR;
    main_kernel<<<(total + 255) / 256, 256>>>(x, mean, stdv, out, nplanes);
}

// round 13
// speedup vs baseline: 1.1551x; 1.1551x over previous
#include <cuda_runtime.h>

#define HW 50176
#define W_ 224
#define H_ 224
#define SEGS 8
#define SEG_ROWS 28          // 224 / 8
#define QPR 56               // quads per row (224/4)
#define RG  56               // 4-row groups per plane (224/4)

__device__ float g_part[1024 * SEGS];   // per-(image,segment) partial sums
__device__ float g_gm[1024];            // per-image gray mean
__device__ int   g_cnt[1024];           // arrival tickets (zero-init, self-resetting)

// ---------------------------------------------------------------------------
// Kernel 1: R10 reduce byte-for-byte + early PDL trigger.
// FROZEN accumulation ORDER (fixes gm's fp value -> solarize flips).
// ---------------------------------------------------------------------------
__global__ void __launch_bounds__(256)
reduce_kernel(const float* __restrict__ x,
              const float* __restrict__ mean,
              const float* __restrict__ stdv) {
#if __CUDA_ARCH__ >= 900
    cudaTriggerProgrammaticLaunchCompletion();   // let main fill freed SM slots
#endif
    const int b = blockIdx.x >> 3;
    const int s = blockIdx.x & 7;
    const float* p = x + (size_t)b * 3 * HW + s * SEG_ROWS * W_;

    const float gw0 = 0.299f * stdv[0];
    const float gw1 = 0.587f * stdv[1];
    const float gw2 = 0.114f * stdv[2];

    const int npix = SEG_ROWS * W_ / 4;   // 1568 quads
    float acc = 0.f;

    int i = threadIdx.x;
    float4 a0 = *(const float4*)(p + i * 4);
    float4 a1 = *(const float4*)(p + HW + i * 4);
    float4 a2 = *(const float4*)(p + 2 * HW + i * 4);
    float4 b0 = *(const float4*)(p + (i + 256) * 4);
    float4 b1 = *(const float4*)(p + HW + (i + 256) * 4);
    float4 b2 = *(const float4*)(p + 2 * HW + (i + 256) * 4);

    while (i < npix) {
        const int pf = i + 512;            // distance-2 prefetch
        float4 c0, c1, c2;
        if (pf < npix) {
            c0 = *(const float4*)(p + pf * 4);
            c1 = *(const float4*)(p + HW + pf * 4);
            c2 = *(const float4*)(p + 2 * HW + pf * 4);
        }

        const int pix = i * 4;
        const int lr = pix / W_;
        const int cc0 = pix - lr * W_;
        const int gr = s * SEG_ROWS + lr;
        const float ny = (gr == 0 || gr == H_ - 1) ? 2.f : 3.f;

        float e0[4] = {a0.x, a0.y, a0.z, a0.w};
        float e1[4] = {a1.x, a1.y, a1.z, a1.w};
        float e2[4] = {a2.x, a2.y, a2.z, a2.w};

        if (cc0 != 0 && cc0 != W_ - 4) {
            const float coef = 0.64f + 0.36f * (ny * 3.f + 4.f) * (1.f / 13.f);
#pragma unroll
            for (int j = 0; j < 4; j++) {
                const float gx = gw0 * e0[j] + gw1 * e1[j] + gw2 * e2[j];
                acc += coef * gx;
            }
        } else {
#pragma unroll
            for (int j = 0; j < 4; j++) {
                const int c = cc0 + j;
                const float nxw = (c == 0 || c == W_ - 1) ? 2.f : 3.f;
                const float coef = 0.64f + 0.36f * (ny * nxw + 4.f) * (1.f / 13.f);
                const float gx = gw0 * e0[j] + gw1 * e1[j] + gw2 * e2[j];
                acc += coef * gx;
            }
        }

        a0 = b0; a1 = b1; a2 = b2;
        b0 = c0; b1 = c1; b2 = c2;
        i += 256;
    }

    __shared__ float red[8];
    __shared__ bool amLast;
#pragma unroll
    for (int off = 16; off > 0; off >>= 1)
        acc += __shfl_down_sync(0xffffffffu, acc, off);
    const int lane = threadIdx.x & 31;
    const int warp = threadIdx.x >> 5;
    if (lane == 0) red[warp] = acc;
    __syncthreads();
    if (threadIdx.x == 0) {
        float t = 0.f;
#pragma unroll
        for (int w = 0; w < 8; w++) t += red[w];
        g_part[blockIdx.x] = t;
        __threadfence();
        const int old = atomicAdd(&g_cnt[b], 1);
        amLast = (old == SEGS - 1);
    }
    __syncthreads();
    if (amLast && threadIdx.x == 0) {
        __threadfence();
        float ps = 0.f;
#pragma unroll
        for (int k = 0; k < SEGS; k++) ps += g_part[b * SEGS + k];
        const double SC = 0.64 * (double)HW + 0.36 * (448900.0 + 4.0 * HW) / 13.0;
        const float cm = 0.299f * mean[0] + 0.587f * mean[1] + 0.114f * mean[2];
        g_gm[b] = (ps + cm * (float)SC) * (1.0f / (float)HW);
        g_cnt[b] = 0;                      // reset for next graph replay
    }
}

// ---------------------------------------------------------------------------
// Kernel 2: R10 main, math byte-for-byte. PDL restructure: gm-independent
// preamble before cudaGridDependencySynchronize, gm read + compute after.
// Launched WITHOUT the PDL attribute (fallback), the sync is a no-op wait
// (upstream already complete) -> identical behavior to R10.
// ---------------------------------------------------------------------------
__global__ void __launch_bounds__(256)
main_kernel(const float* __restrict__ x,
            const float* __restrict__ mean,
            const float* __restrict__ stdv,
            float* __restrict__ out,
            int nplanes) {
    const int idx = blockIdx.x * 256 + threadIdx.x;
    const int q = idx % QPR;                  // column quad 0..55
    const int t2 = idx / QPR;
    const int rg = t2 % RG;                   // row group 0..55
    int plane = t2 / RG;
    if (plane >= nplanes) return;
    plane = nplanes - 1 - plane;              // reverse traversal for L2 reuse

    const int b = plane / 3;
    const int ch = plane - b * 3;
    const float m = mean[ch];
    const float sd = stdv[ch];
    const float inv_sd = 1.0f / sd;
    const float nmo = -m * inv_sd;

    const float C1 = (float)(0.4096 * (0.64 + 1.44 / 13.0));
    const float C2 = (float)(0.4096 * 0.36 / 13.0);

    const float* p = x + (size_t)plane * HW;
    const int c4 = q * 4;
    const int r0 = rg * 4;

    // ======== gm-independent preamble (overlaps with reduce under PDL) ======
    float4 v[6];
#pragma unroll
    for (int k = 0; k < 6; k++) {
        const int row = r0 - 1 + k;
        if (row >= 0 && row < H_) {
            float4 u = *(const float4*)(p + row * W_ + c4);
            v[k].x = fmaf(u.x, sd, m);
            v[k].y = fmaf(u.y, sd, m);
            v[k].z = fmaf(u.z, sd, m);
            v[k].w = fmaf(u.w, sd, m);
        } else {
            v[k] = make_float4(0.f, 0.f, 0.f, 0.f);
        }
    }

    const unsigned lane = threadIdx.x & 31;
    float L[6], R[6];
#pragma unroll
    for (int k = 0; k < 6; k++) {
        L[k] = __shfl_up_sync(0xffffffffu, v[k].w, 1);
        R[k] = __shfl_down_sync(0xffffffffu, v[k].x, 1);
    }
    if (q == 0) {
#pragma unroll
        for (int k = 0; k < 6; k++) L[k] = 0.f;
    } else if (lane == 0) {
#pragma unroll
        for (int k = 0; k < 6; k++) {
            const int row = r0 - 1 + k;
            L[k] = (row >= 0 && row < H_) ? fmaf(p[row * W_ + c4 - 1], sd, m) : 0.f;
        }
    }
    if (q == QPR - 1) {
#pragma unroll
        for (int k = 0; k < 6; k++) R[k] = 0.f;
    } else if (lane == 31) {
#pragma unroll
        for (int k = 0; k < 6; k++) {
            const int row = r0 - 1 + k;
            R[k] = (row >= 0 && row < H_) ? fmaf(p[row * W_ + c4 + 4], sd, m) : 0.f;
        }
    }

    // ======== wait for reduce grid completion, then read gm ========
#if __CUDA_ARCH__ >= 900
    cudaGridDependencySynchronize();
#endif
    const float gm = g_gm[b];
    const float G  = (float)(0.64 * 0.36) * gm;

    // ======== compute + store (unchanged) ========
    float* ob = out + (size_t)plane * HW + r0 * W_ + c4;

#pragma unroll
    for (int o = 0; o < 4; o++) {
        const float cs0 = L[o]   + L[o + 1]   + L[o + 2];
        const float cs1 = v[o].x + v[o + 1].x + v[o + 2].x;
        const float cs2 = v[o].y + v[o + 1].y + v[o + 2].y;
        const float cs3 = v[o].z + v[o + 1].z + v[o + 2].z;
        const float cs4 = v[o].w + v[o + 1].w + v[o + 2].w;
        const float cs5 = R[o]   + R[o + 1]   + R[o + 2];

        const float cen[4] = {v[o + 1].x, v[o + 1].y, v[o + 1].z, v[o + 1].w};
        const float tot[4] = {cs0 + cs1 + cs2, cs1 + cs2 + cs3,
                              cs2 + cs3 + cs4, cs3 + cs4 + cs5};

        float4 ov;
        float* op = (float*)&ov;
#pragma unroll
        for (int j = 0; j < 4; j++) {
            const float y2 = fmaf(cen[j], C1, fmaf(tot[j], C2, G));
            const float z = (y2 < 0.3f) ? y2 : 1.0f - y2;
            op[j] = fmaf(z, inv_sd, nmo);
        }
        __stwt((float4*)(ob + o * W_), ov);    // write-through, no L2 allocate
    }
}

extern "C" void kernel_launch(void* const* d_in, const int* in_sizes, int n_in,
                              void* d_out, int out_size) {
    const float* x    = (const float*)d_in[0];
    const float* mean = (const float*)d_in[1];
    const float* stdv = (const float*)d_in[2];
    float* out = (float*)d_out;

    const int B = in_sizes[0] / (3 * HW);
    const int nplanes = B * 3;

    reduce_kernel<<<B * SEGS, 256>>>(x, mean, stdv);

    const int total = nplanes * RG * QPR;
    const int gblocks = (total + 255) / 256;

    // Try PDL launch; on ANY failure fall back to a plain launch (identical
    // behavior to R10 -- the in-kernel sync then just sees a completed grid).
    cudaLaunchConfig_t cfg = {};
    cfg.gridDim = dim3(gblocks);
    cfg.blockDim = dim3(256);
    cfg.dynamicSmemBytes = 0;
    cfg.stream = 0;
    cudaLaunchAttribute attrs[1];
    attrs[0].id = cudaLaunchAttributeProgrammaticStreamSerialization;
    attrs[0].val.programmaticStreamSerializationAllowed = 1;
    cfg.attrs = attrs;
    cfg.numAttrs = 1;

    cudaError_t err = cudaLaunchKernelEx(&cfg, main_kernel,
                                         x, mean, stdv, out, nplanes);
    if (err != cudaSuccess) {
        (void)cudaGetLastError();              // clear sticky error
        main_kernel<<<gblocks, 256>>>(x, mean, stdv, out, nplanes);
    }
}